// round 15
// baseline (speedup 1.0000x reference)
#include <cuda_runtime.h>
#include <math.h>

#define NB 262144
#define NP 8
#define NT 256
#define NBLOCKS (NB / NT)

__device__ double g_part[NBLOCKS];
__device__ unsigned int g_ticket;

__global__ void __launch_bounds__(NT, 4)
ciou_kernel(const float* __restrict__ A, const float* __restrict__ Bm,
            float* __restrict__ out) {
    const int tid = threadIdx.x;
    const int b   = blockIdx.x * NT + tid;

    double val;
    {
        // ---- load both octagons (registers; const indexing everywhere) ----
        float axv[NP], ayv[NP], bxv[NP], byv[NP];
        const float4* pa4 = (const float4*)(A  + (size_t)b * 16);
        const float4* pb4 = (const float4*)(Bm + (size_t)b * 16);
        #pragma unroll
        for (int i = 0; i < 4; i++) {
            float4 fa = pa4[i], fb = pb4[i];
            axv[2*i]   = fa.x; ayv[2*i]   = fa.y;
            axv[2*i+1] = fa.z; ayv[2*i+1] = fa.w;
            bxv[2*i]   = fb.x; byv[2*i]   = fb.y;
            bxv[2*i+1] = fb.z; byv[2*i+1] = fb.w;
        }

        // ---- shoelace areas (vertices CCW by construction) ----
        float area_a = 0.f, area_b = 0.f;
        #pragma unroll
        for (int i = 0; i < NP; i++) {
            int j = (i + 1) & 7;
            area_a += axv[i]*ayv[j] - ayv[i]*axv[j];
            area_b += bxv[i]*byv[j] - byv[i]*bxv[j];
        }
        area_a *= 0.5f; area_b *= 0.5f;

        // ---- intersection area via Green's theorem + Liang-Barsky ----
        // Interval update is select-free: g = cd*1e38 carries cd's sign as
        // +-huge/inf, gating r into the max (entering) or min (leaving) bound
        // through pure FMNMX. cd==0.f exactly is measure-zero; near-parallel
        // flows correctly through the +-huge quotient.
        float acc2 = 0.f;

        {   // --- A edges vs B's half-planes ---
            float pex[NP], pey[NP], pkc[NP];
            #pragma unroll
            for (int j = 0; j < NP; j++) {
                int jk = (j + 1) & 7;
                pex[j] = bxv[jk] - bxv[j];
                pey[j] = byv[jk] - byv[j];
                pkc[j] = pex[j]*byv[j] - pey[j]*bxv[j];
            }
            #pragma unroll
            for (int i = 0; i < NP; i++) {
                int ik = (i + 1) & 7;
                float px = axv[i],        py = ayv[i];
                float dx = axv[ik] - px,  dy = ayv[ik] - py;
                float t0 = 0.f, t1 = 1.f;
                #pragma unroll
                for (int j = 0; j < NP; j++) {
                    float c0 = fmaf(pex[j], py, -fmaf(pey[j], px, pkc[j]));
                    float cd = pex[j]*dy - pey[j]*dx;
                    float r  = __fdividef(-c0, cd);
                    float g  = cd * 1e38f;
                    t0 = fmaxf(t0, fminf(r, g));
                    t1 = fminf(t1, fmaxf(r, g));
                }
                if (t1 > t0) {
                    float qx0 = fmaf(t0, dx, px), qy0 = fmaf(t0, dy, py);
                    float qx1 = fmaf(t1, dx, px), qy1 = fmaf(t1, dy, py);
                    acc2 += qx0*qy1 - qy0*qx1;
                }
            }
        }
        {   // --- B edges vs A's half-planes ---
            float pex[NP], pey[NP], pkc[NP];
            #pragma unroll
            for (int j = 0; j < NP; j++) {
                int jk = (j + 1) & 7;
                pex[j] = axv[jk] - axv[j];
                pey[j] = ayv[jk] - ayv[j];
                pkc[j] = pex[j]*ayv[j] - pey[j]*axv[j];
            }
            #pragma unroll
            for (int i = 0; i < NP; i++) {
                int ik = (i + 1) & 7;
                float px = bxv[i],        py = byv[i];
                float dx = bxv[ik] - px,  dy = byv[ik] - py;
                float t0 = 0.f, t1 = 1.f;
                #pragma unroll
                for (int j = 0; j < NP; j++) {
                    float c0 = fmaf(pex[j], py, -fmaf(pey[j], px, pkc[j]));
                    float cd = pex[j]*dy - pey[j]*dx;
                    float r  = __fdividef(-c0, cd);
                    float g  = cd * 1e38f;
                    t0 = fmaxf(t0, fminf(r, g));
                    t1 = fminf(t1, fmaxf(r, g));
                }
                if (t1 > t0) {
                    float qx0 = fmaf(t0, dx, px), qy0 = fmaf(t0, dy, py);
                    float qx1 = fmaf(t1, dx, px), qy1 = fmaf(t1, dy, py);
                    acc2 += qx0*qy1 - qy0*qx1;
                }
            }
        }
        float inter = fmaxf(0.5f * acc2, 0.f);

        // ---- convex hull of all 16 points (lean register Jarvis march) ----
        int   si  = 0;
        float spx = axv[0], spy = ayv[0];
        #pragma unroll
        for (int i = 1; i < 16; i++) {
            float pix = (i < 8) ? axv[i] : bxv[i-8];
            float piy = (i < 8) ? ayv[i] : byv[i-8];
            bool better = (piy < spy) || (piy == spy && pix < spx);
            if (better) { si = i; spx = pix; spy = piy; }
        }
        int   cur = si;
        float acc = 0.f, cpx = spx, cpy = spy;
        #pragma unroll 1
        for (int step = 0; step < 16; step++) {
            int   nxt = (cur == 0) ? 1 : 0;
            float vnx = ((cur == 0) ? axv[1] : axv[0]) - cpx;
            float vny = ((cur == 0) ? ayv[1] : ayv[0]) - cpy;
            #pragma unroll
            for (int p = 0; p < 16; p++) {
                float pxp = (p < 8) ? axv[p] : bxv[p-8];
                float pyp = (p < 8) ? ayv[p] : byv[p-8];
                float vx = pxp - cpx, vy = pyp - cpy;
                float cr = vnx*vy - vny*vx;
                bool take = (p != cur) && (cr < 0.f);
                if (take) { nxt = p; vnx = vx; vny = vy; }
            }
            acc += cpx*vny - cpy*vnx;    // cross(cp, cp+vn)
            if (nxt == si) break;
            cpx += vnx; cpy += vny;
            cur = nxt;
        }
        float ch = 0.5f * acc;

        // ---- CIoU ----
        float uni = area_a + area_b - inter;
        float iou = inter / uni;
        val = (double)(iou - (ch - uni) / ch);
    }

    // ---- deterministic block reduction (8 warps) ----
    #pragma unroll
    for (int o = 16; o > 0; o >>= 1)
        val += __shfl_down_sync(0xffffffffu, val, o);
    __shared__ double ws[NT / 32];
    __shared__ bool is_last;
    int lane = threadIdx.x & 31;
    int w    = threadIdx.x >> 5;
    if (lane == 0) ws[w] = val;
    __syncthreads();
    if (w == 0) {
        val = (lane < (NT / 32)) ? ws[lane] : 0.0;
        #pragma unroll
        for (int o = 4; o > 0; o >>= 1)
            val += __shfl_down_sync(0xffffffffu, val, o);
        if (lane == 0) g_part[blockIdx.x] = val;
    }

    // ---- last block folds the partials (deterministic fixed-order sum) ----
    __threadfence();
    if (threadIdx.x == 0) {
        unsigned int t = atomicAdd(&g_ticket, 1u);
        is_last = (t == NBLOCKS - 1);
    }
    __syncthreads();
    if (is_last) {
        __threadfence();
        double v = 0.0;
        for (int i = threadIdx.x; i < NBLOCKS; i += NT) v += g_part[i];
        #pragma unroll
        for (int o = 16; o > 0; o >>= 1)
            v += __shfl_down_sync(0xffffffffu, v, o);
        if (lane == 0) ws[w] = v;
        __syncthreads();
        if (w == 0) {
            v = (lane < (NT / 32)) ? ws[lane] : 0.0;
            #pragma unroll
            for (int o = 4; o > 0; o >>= 1)
                v += __shfl_down_sync(0xffffffffu, v, o);
            if (lane == 0) {
                out[0] = (float)(v / (double)NB);
                g_ticket = 0;   // reset for next graph replay
            }
        }
    }
}

extern "C" void kernel_launch(void* const* d_in, const int* in_sizes, int n_in,
                              void* d_out, int out_size) {
    const float* a = (const float*)d_in[0];
    const float* b = (const float*)d_in[1];
    ciou_kernel<<<NBLOCKS, NT>>>(a, b, (float*)d_out);
}